// round 15
// baseline (speedup 1.0000x reference)
#include <cuda_runtime.h>

#define BB   4
#define NN   512
#define FD   256
#define AD   256
#define DP   64
#define PD   128
#define ROWS (BB*NN)          /* 2048 */
#define NPAIR (BB*NN*NN)      /* 1048576 */
#define EPSF 1e-3f
#define SCAL 0.0625f          /* 1/sqrt(256) */

#define BIAS_BLOCKS 4096      /* 1048576 rows / 256 rows per block */
#define T_TILES     128       /* (2048/64) * (256/64) */

// ---------------- scratch (device globals; no allocation allowed) ----------
__device__ float d_Fn[ROWS*FD];
__device__ float d_M[FD*FD];         // Wq @ Wk^T
__device__ float d_T[ROWS*FD];       // Fn @ M
__device__ float d_vsum[ROWS];
__device__ float d_gw[DP];
__device__ float d_sgw;
__device__ float d_bconst;
__device__ float d_wvsum[FD];
__device__ float d_bias[NPAIR];
__device__ float d_S0[NPAIR];        // split-K partial (K   0.. 63)
__device__ float d_S1[NPAIR];        // split-K partial (K  64..127)
__device__ float d_S2[NPAIR];        // split-K partial (K 128..191)
__device__ float d_S3[NPAIR];        // split-K partial (K 192..255)

// ---------------- helpers ---------------------------------------------------
__device__ __forceinline__ float warp_sum(float v) {
    #pragma unroll
    for (int o = 16; o > 0; o >>= 1) v += __shfl_xor_sync(0xffffffffu, v, o);
    return v;
}
__device__ __forceinline__ float warp_max(float v) {
    #pragma unroll
    for (int o = 16; o > 0; o >>= 1) v = fmaxf(v, __shfl_xor_sync(0xffffffffu, v, o));
    return v;
}
__device__ __forceinline__ unsigned long long pack2(float lo, float hi) {
    unsigned long long r;
    asm("mov.b64 %0, {%1, %2};" : "=l"(r) : "f"(lo), "f"(hi));
    return r;
}
__device__ __forceinline__ void ffma2(unsigned long long& d,
                                      unsigned long long a,
                                      unsigned long long b) {
    asm("fma.rn.f32x2 %0, %1, %2, %0;" : "+l"(d) : "l"(a), "l"(b));
}
__device__ __forceinline__ float2 unpack2(unsigned long long v) {
    float2 f;
    asm("mov.b64 {%0, %1}, %2;" : "=f"(f.x), "=f"(f.y) : "l"(v));
    return f;
}

// ---------------- K1: prep + mgemm  (grid 273 x 256) ------------------------
__global__ void __launch_bounds__(256)
prep_mgemm_kernel(const float* __restrict__ Wq,
                  const float* __restrict__ Wk,
                  const float* __restrict__ Wv,
                  const float* __restrict__ gp,
                  const float* __restrict__ bp,
                  const float* __restrict__ Wpt,
                  const float* __restrict__ bpt,
                  const float* __restrict__ Wph) {
    int tid = threadIdx.x;

    if (blockIdx.x < 16) {
        __shared__ float As[16][68];
        __shared__ float Bs[16][68];
        int f0 = (blockIdx.x >> 2) * 64;
        int g0 = (blockIdx.x & 3) * 64;
        int lm = tid >> 2;
        int lk = (tid & 3) * 4;
        int ty = tid >> 4, tx = tid & 15;

        float acc[4][4] = {};
        for (int kt = 0; kt < AD; kt += 16) {
            float4 a = *(const float4*)&Wq[(f0 + lm)*AD + kt + lk];
            As[lk+0][lm] = a.x; As[lk+1][lm] = a.y;
            As[lk+2][lm] = a.z; As[lk+3][lm] = a.w;
            float4 c = *(const float4*)&Wk[(g0 + lm)*AD + kt + lk];
            Bs[lk+0][lm] = c.x; Bs[lk+1][lm] = c.y;
            Bs[lk+2][lm] = c.z; Bs[lk+3][lm] = c.w;
            __syncthreads();
            #pragma unroll
            for (int kf = 0; kf < 16; kf++) {
                float4 av = *(const float4*)&As[kf][ty*4];
                float4 bv = *(const float4*)&Bs[kf][tx*4];
                float aa[4] = {av.x, av.y, av.z, av.w};
                float bb[4] = {bv.x, bv.y, bv.z, bv.w};
                #pragma unroll
                for (int i = 0; i < 4; i++)
                    #pragma unroll
                    for (int j = 0; j < 4; j++)
                        acc[i][j] += aa[i] * bb[j];
            }
            __syncthreads();
        }
        #pragma unroll
        for (int i = 0; i < 4; i++)
            #pragma unroll
            for (int j = 0; j < 4; j++)
                d_M[(f0 + ty*4 + i)*FD + g0 + tx*4 + j] = acc[i][j];
    } else if (blockIdx.x < 272) {
        int f = blockIdx.x - 16;
        __shared__ float s_w[8];
        int w = tid >> 5, l = tid & 31;
        float s = warp_sum(Wv[f*AD + tid]);
        if (l == 0) s_w[w] = s;
        __syncthreads();
        if (tid == 0) {
            float acc = 0.f;
            #pragma unroll
            for (int i = 0; i < 8; i++) acc += s_w[i];
            d_wvsum[f] = acc;
        }
    } else {
        __shared__ float red[256];
        int c = tid >> 1;
        int j = tid & 1;
        float we = 0.f;
        if (tid < 128) {
            #pragma unroll
            for (int i = 0; i < 16; i++) {
                float4 a = *(const float4*)&Wpt[c*PD + j*64 + i*4];
                float4 b = *(const float4*)&Wph[j*64 + i*4];
                we += a.x*b.x + a.y*b.y + a.z*b.z + a.w*b.w;
            }
            we += __shfl_xor_sync(0xffffffffu, we, 1);
            if (j == 0) d_gw[c] = gp[c] * we;
        }
        float v_sgw = (tid < 128 && j == 0) ? gp[c] * we : 0.f;
        float v_bc  = (tid < 128 && j == 0) ? bp[c] * we : 0.f;
        float v_bpt = (tid < 128) ? bpt[tid] * Wph[tid] : 0.f;

        red[tid] = v_sgw; __syncthreads();
        #pragma unroll
        for (int o = 128; o > 0; o >>= 1) { if (tid < o) red[tid] += red[tid+o]; __syncthreads(); }
        if (tid == 0) d_sgw = red[0];
        __syncthreads();
        red[tid] = v_bc + v_bpt; __syncthreads();
        #pragma unroll
        for (int o = 128; o > 0; o >>= 1) { if (tid < o) red[tid] += red[tid+o]; __syncthreads(); }
        if (tid == 0) d_bconst = red[0];
    }
}

// ---------------- K2: LayerNorm(F) -> Fn, vsum ------------------------------
__global__ void __launch_bounds__(256)
lnf_kernel(const float* __restrict__ F,
           const float* __restrict__ gf,
           const float* __restrict__ bf) {
    __shared__ float s_a[8], s_b[8];
    int r = blockIdx.x;
    int t = threadIdx.x;
    int w = t >> 5, l = t & 31;
    float x = F[r*FD + t];

    float sa = warp_sum(x);
    float sb = warp_sum(x*x);
    if (l == 0) { s_a[w] = sa; s_b[w] = sb; }
    __syncthreads();
    float ts = 0.f, tq = 0.f;
    #pragma unroll
    for (int i = 0; i < 8; i++) { ts += s_a[i]; tq += s_b[i]; }
    float mu = ts * (1.f/FD);
    float rstd = rsqrtf(tq * (1.f/FD) - mu*mu + EPSF);
    float fn = (x - mu) * rstd * gf[t] + bf[t];
    d_Fn[r*FD + t] = fn;

    __syncthreads();
    float sv = warp_sum(fn * d_wvsum[t]);
    if (l == 0) s_a[w] = sv;
    __syncthreads();
    if (t == 0) {
        float acc = 0.f;
        #pragma unroll
        for (int i = 0; i < 8; i++) acc += s_a[i];
        d_vsum[r] = acc;
    }
}

// ---------------- K3: fused  T = Fn @ M (first)  ||  bias(D sweep) ----------
__global__ void __launch_bounds__(256, 8)
bias_t_kernel(const float* __restrict__ Dm) {
    int tid = threadIdx.x;

    if (blockIdx.x >= T_TILES) {
        int w = tid >> 5, l = tid & 31;
        int sub = l & 7;          // column group: 2 float4 slots (32B)
        int rr  = l >> 3;         // row within group of 4

        float4 g0 = *(const float4*)&d_gw[sub*8];
        float4 g1 = *(const float4*)&d_gw[sub*8 + 4];
        float sgw = d_sgw, bconst = d_bconst;

        int rowbase = (blockIdx.x - T_TILES) * 256 + w * 32 + rr;
        #pragma unroll
        for (int it = 0; it < 8; it++) {
            int row = rowbase + it * 4;
            const float4* p = (const float4*)&Dm[(size_t)row * DP];
            float4 c0 = __ldcs(p + sub*2);
            float4 c1 = __ldcs(p + sub*2 + 1);

            float s1 = (c0.x+c0.y+c0.z+c0.w) + (c1.x+c1.y+c1.z+c1.w);
            float s2 = c0.x*c0.x+c0.y*c0.y+c0.z*c0.z+c0.w*c0.w
                     + c1.x*c1.x+c1.y*c1.y+c1.z*c1.z+c1.w*c1.w;
            float s3 = c0.x*g0.x+c0.y*g0.y+c0.z*g0.z+c0.w*g0.w
                     + c1.x*g1.x+c1.y*g1.y+c1.z*g1.z+c1.w*g1.w;

            #pragma unroll
            for (int o = 1; o < 8; o <<= 1) {
                s1 += __shfl_xor_sync(0xffffffffu, s1, o);
                s2 += __shfl_xor_sync(0xffffffffu, s2, o);
                s3 += __shfl_xor_sync(0xffffffffu, s3, o);
            }
            if (sub == 0) {
                float mu = s1 * (1.f/DP);
                float var = s2 * (1.f/DP) - mu*mu;
                float rstd = rsqrtf(var + EPSF);
                d_bias[row] = rstd * (s3 - mu*sgw) + bconst;
            }
        }
    } else {
        // ---- T[2048 x 256] = Fn[2048 x 256] @ M[256 x 256] (NN) ----
        __shared__ float As[16][68];
        __shared__ float Bs[16][68];
        int t2 = blockIdx.x;
        int bm = t2 & 31;
        int bn = t2 >> 5;
        int row0 = bm * 64;
        int n0   = bn * 64;

        int lm = tid >> 2;
        int lk = (tid & 3) * 4;
        int bk = tid >> 4;
        int bn4 = (tid & 15) * 4;
        int ty = tid >> 4, tx = tid & 15;

        float acc[4][4] = {};
        for (int kt = 0; kt < FD; kt += 16) {
            float4 a = *(const float4*)&d_Fn[(row0 + lm)*FD + kt + lk];
            As[lk+0][lm] = a.x; As[lk+1][lm] = a.y;
            As[lk+2][lm] = a.z; As[lk+3][lm] = a.w;
            float4 b = *(const float4*)&d_M[(kt + bk)*FD + n0 + bn4];
            Bs[bk][bn4+0] = b.x; Bs[bk][bn4+1] = b.y;
            Bs[bk][bn4+2] = b.z; Bs[bk][bn4+3] = b.w;
            __syncthreads();
            #pragma unroll
            for (int kf = 0; kf < 16; kf++) {
                float4 av = *(const float4*)&As[kf][ty*4];
                float4 bv = *(const float4*)&Bs[kf][tx*4];
                float aa[4] = {av.x, av.y, av.z, av.w};
                float bb[4] = {bv.x, bv.y, bv.z, bv.w};
                #pragma unroll
                for (int i = 0; i < 4; i++)
                    #pragma unroll
                    for (int j = 0; j < 4; j++)
                        acc[i][j] += aa[i] * bb[j];
            }
            __syncthreads();
        }
        #pragma unroll
        for (int i = 0; i < 4; i++) {
            int r = row0 + ty*4 + i;
            #pragma unroll
            for (int j = 0; j < 4; j++)
                d_T[r*FD + n0 + tx*4 + j] = acc[i][j];
        }
    }
}

// ---------------- K4: split-K(4) S-GEMM, 128x128 / 8x8 tile, f32x2 ----------
// grid (4, 4, 16): z = b*4 + quarter; K-chunk 64 per block.
__global__ void __launch_bounds__(256)
s_gemm_kernel() {
    __shared__ float As[8][132];   // row stride 528B (16B-multiple)
    __shared__ float Bs[8][132];
    int z  = blockIdx.z;
    int b  = z >> 2;
    int quarter = z & 3;
    int q0 = blockIdx.y * 128;
    int k0 = blockIdx.x * 128;
    const float* A  = d_T  + b*NN*FD;
    const float* Bm = d_Fn + b*NN*FD;
    float* Sp = (quarter == 0) ? d_S0 : (quarter == 1) ? d_S1
              : (quarter == 2) ? d_S2 : d_S3;

    int tid = threadIdx.x;
    int lrow = tid >> 1;            // 0..127
    int lk4  = (tid & 1) * 4;       // 0 or 4
    int ty = tid >> 4, tx = tid & 15;

    int kbase = quarter * 64;
    unsigned long long acc2[8][4] = {};   // (i, j-pair) packed f32x2

    float4 pa = *(const float4*)&A [(q0 + lrow)*FD + kbase + lk4];
    float4 pb = *(const float4*)&Bm[(k0 + lrow)*FD + kbase + lk4];

    for (int c = 0; c < 8; c++) {
        As[lk4+0][lrow] = pa.x; As[lk4+1][lrow] = pa.y;
        As[lk4+2][lrow] = pa.z; As[lk4+3][lrow] = pa.w;
        Bs[lk4+0][lrow] = pb.x; Bs[lk4+1][lrow] = pb.y;
        Bs[lk4+2][lrow] = pb.z; Bs[lk4+3][lrow] = pb.w;
        __syncthreads();
        if (c < 7) {
            int kt = kbase + (c + 1) * 8;
            pa = *(const float4*)&A [(q0 + lrow)*FD + kt + lk4];
            pb = *(const float4*)&Bm[(k0 + lrow)*FD + kt + lk4];
        }
        #pragma unroll
        for (int k = 0; k < 8; k++) {
            float a[8], bt[8];
            *(float4*)&a[0]  = *(const float4*)&As[k][ty*8];
            *(float4*)&a[4]  = *(const float4*)&As[k][ty*8 + 4];
            *(float4*)&bt[0] = *(const float4*)&Bs[k][tx*8];
            *(float4*)&bt[4] = *(const float4*)&Bs[k][tx*8 + 4];
            unsigned long long bp[4];
            #pragma unroll
            for (int j2 = 0; j2 < 4; j2++) bp[j2] = pack2(bt[2*j2], bt[2*j2+1]);
            #pragma unroll
            for (int i = 0; i < 8; i++) {
                unsigned long long ap = pack2(a[i], a[i]);
                #pragma unroll
                for (int j2 = 0; j2 < 4; j2++) ffma2(acc2[i][j2], ap, bp[j2]);
            }
        }
        __syncthreads();
    }
    #pragma unroll
    for (int i = 0; i < 8; i++) {
        int q = q0 + ty*8 + i;
        int idx = (b*NN + q)*NN + k0 + tx*8;
        float2 p0 = unpack2(acc2[i][0]);
        float2 p1 = unpack2(acc2[i][1]);
        float2 p2 = unpack2(acc2[i][2]);
        float2 p3 = unpack2(acc2[i][3]);
        float4 o0, o1;
        o0.x = p0.x; o0.y = p0.y; o0.z = p1.x; o0.w = p1.y;
        o1.x = p2.x; o1.y = p2.y; o1.z = p3.x; o1.w = p3.y;
        *(float4*)&Sp[idx]     = o0;
        *(float4*)&Sp[idx + 4] = o1;
    }
}

// ---------------- K5: softmax, one warp per row -----------------------------
__global__ void __launch_bounds__(256)
softmax_out_kernel(float* __restrict__ out) {
    int wid = threadIdx.x >> 5, l = threadIdx.x & 31;
    int r = blockIdx.x * 8 + wid;
    int b = r >> 9;

    float s[16];
    #pragma unroll
    for (int c = 0; c < 4; c++) {
        int idx = r*NN + c*128 + l*4;
        float4 x0 = *(const float4*)&d_S0[idx];
        float4 x1 = *(const float4*)&d_S1[idx];
        float4 x2 = *(const float4*)&d_S2[idx];
        float4 x3 = *(const float4*)&d_S3[idx];
        float4 xc = *(const float4*)&d_bias[idx];
        s[c*4+0] = SCAL * (x0.x + x1.x + x2.x + x3.x + xc.x);
        s[c*4+1] = SCAL * (x0.y + x1.y + x2.y + x3.y + xc.y);
        s[c*4+2] = SCAL * (x0.z + x1.z + x2.z + x3.z + xc.z);
        s[c*4+3] = SCAL * (x0.w + x1.w + x2.w + x3.w + xc.w);
    }
    float m = s[0];
    #pragma unroll
    for (int i = 1; i < 16; i++) m = fmaxf(m, s[i]);
    m = warp_max(m);

    float se = 0.f, sv = 0.f;
    #pragma unroll
    for (int c = 0; c < 4; c++) {
        float4 vv = *(const float4*)&d_vsum[b*NN + c*128 + l*4];
        float e0 = __expf(s[c*4+0] - m);
        float e1 = __expf(s[c*4+1] - m);
        float e2 = __expf(s[c*4+2] - m);
        float e3 = __expf(s[c*4+3] - m);
        se += e0 + e1 + e2 + e3;
        sv += e0*vv.x + e1*vv.y + e2*vv.z + e3*vv.w;
    }
    se = warp_sum(se);
    sv = warp_sum(sv);
    if (l == 0) out[r] = sv / se;
}

// ---------------- launch ----------------------------------------------------
extern "C" void kernel_launch(void* const* d_in, const int* in_sizes, int n_in,
                              void* d_out, int out_size) {
    const float* F   = (const float*)d_in[0];
    const float* Dm  = (const float*)d_in[1];
    const float* Wq  = (const float*)d_in[2];
    const float* Wk  = (const float*)d_in[3];
    const float* Wv  = (const float*)d_in[4];
    const float* gf  = (const float*)d_in[5];
    const float* bf  = (const float*)d_in[6];
    const float* gp  = (const float*)d_in[7];
    const float* bp  = (const float*)d_in[8];
    const float* Wpt = (const float*)d_in[9];
    const float* bpt = (const float*)d_in[10];
    const float* Wph = (const float*)d_in[11];
    float* out = (float*)d_out;

    prep_mgemm_kernel<<<273, 256>>>(Wq, Wk, Wv, gp, bp, Wpt, bpt, Wph);
    lnf_kernel<<<ROWS, 256>>>(F, gf, bf);
    bias_t_kernel<<<T_TILES + BIAS_BLOCKS, 256>>>(Dm);
    dim3 g4(4, 4, BB*4);
    s_gemm_kernel<<<g4, 256>>>();
    softmax_out_kernel<<<ROWS/8, 256>>>(out);
}

// round 16
// speedup vs baseline: 1.1000x; 1.1000x over previous
#include <cuda_runtime.h>

#define BB   4
#define NN   512
#define FD   256
#define AD   256
#define DP   64
#define PD   128
#define ROWS (BB*NN)          /* 2048 */
#define NPAIR (BB*NN*NN)      /* 1048576 */
#define EPSF 1e-3f
#define SCAL 0.0625f          /* 1/sqrt(256) */

#define BIAS_BLOCKS 4096      /* 1048576 rows / 256 rows per block */
#define T_TILES     128       /* (2048/64) * (256/64) */

// ---------------- scratch (device globals; no allocation allowed) ----------
__device__ float d_Fn[ROWS*FD];
__device__ float d_M[FD*FD];         // Wq @ Wk^T
__device__ float d_T[ROWS*FD];       // Fn @ M
__device__ float d_vsum[ROWS];
__device__ float d_gw[DP];
__device__ float d_sgw;
__device__ float d_bconst;
__device__ float d_wvsum[FD];
__device__ float d_bias[NPAIR];
__device__ float d_Sa[NPAIR];        // split-K partial (K 0..127)
__device__ float d_Sb[NPAIR];        // split-K partial (K 128..255)

// ---------------- helpers ---------------------------------------------------
__device__ __forceinline__ float warp_sum(float v) {
    #pragma unroll
    for (int o = 16; o > 0; o >>= 1) v += __shfl_xor_sync(0xffffffffu, v, o);
    return v;
}
__device__ __forceinline__ float warp_max(float v) {
    #pragma unroll
    for (int o = 16; o > 0; o >>= 1) v = fmaxf(v, __shfl_xor_sync(0xffffffffu, v, o));
    return v;
}
__device__ __forceinline__ unsigned long long pack2(float lo, float hi) {
    unsigned long long r;
    asm("mov.b64 %0, {%1, %2};" : "=l"(r) : "f"(lo), "f"(hi));
    return r;
}
__device__ __forceinline__ void ffma2(unsigned long long& d,
                                      unsigned long long a,
                                      unsigned long long b) {
    asm("fma.rn.f32x2 %0, %1, %2, %0;" : "+l"(d) : "l"(a), "l"(b));
}
__device__ __forceinline__ float2 unpack2(unsigned long long v) {
    float2 f;
    asm("mov.b64 {%0, %1}, %2;" : "=f"(f.x), "=f"(f.y) : "l"(v));
    return f;
}

// ---------------- K1: prep + mgemm  (grid 273 x 256) ------------------------
__global__ void __launch_bounds__(256)
prep_mgemm_kernel(const float* __restrict__ Wq,
                  const float* __restrict__ Wk,
                  const float* __restrict__ Wv,
                  const float* __restrict__ gp,
                  const float* __restrict__ bp,
                  const float* __restrict__ Wpt,
                  const float* __restrict__ bpt,
                  const float* __restrict__ Wph) {
    int tid = threadIdx.x;

    if (blockIdx.x < 16) {
        __shared__ float As[16][68];
        __shared__ float Bs[16][68];
        int f0 = (blockIdx.x >> 2) * 64;
        int g0 = (blockIdx.x & 3) * 64;
        int lm = tid >> 2;
        int lk = (tid & 3) * 4;
        int ty = tid >> 4, tx = tid & 15;

        float acc[4][4] = {};
        for (int kt = 0; kt < AD; kt += 16) {
            float4 a = *(const float4*)&Wq[(f0 + lm)*AD + kt + lk];
            As[lk+0][lm] = a.x; As[lk+1][lm] = a.y;
            As[lk+2][lm] = a.z; As[lk+3][lm] = a.w;
            float4 c = *(const float4*)&Wk[(g0 + lm)*AD + kt + lk];
            Bs[lk+0][lm] = c.x; Bs[lk+1][lm] = c.y;
            Bs[lk+2][lm] = c.z; Bs[lk+3][lm] = c.w;
            __syncthreads();
            #pragma unroll
            for (int kf = 0; kf < 16; kf++) {
                float4 av = *(const float4*)&As[kf][ty*4];
                float4 bv = *(const float4*)&Bs[kf][tx*4];
                float aa[4] = {av.x, av.y, av.z, av.w};
                float bb[4] = {bv.x, bv.y, bv.z, bv.w};
                #pragma unroll
                for (int i = 0; i < 4; i++)
                    #pragma unroll
                    for (int j = 0; j < 4; j++)
                        acc[i][j] += aa[i] * bb[j];
            }
            __syncthreads();
        }
        #pragma unroll
        for (int i = 0; i < 4; i++)
            #pragma unroll
            for (int j = 0; j < 4; j++)
                d_M[(f0 + ty*4 + i)*FD + g0 + tx*4 + j] = acc[i][j];
    } else if (blockIdx.x < 272) {
        int f = blockIdx.x - 16;
        __shared__ float s_w[8];
        int w = tid >> 5, l = tid & 31;
        float s = warp_sum(Wv[f*AD + tid]);
        if (l == 0) s_w[w] = s;
        __syncthreads();
        if (tid == 0) {
            float acc = 0.f;
            #pragma unroll
            for (int i = 0; i < 8; i++) acc += s_w[i];
            d_wvsum[f] = acc;
        }
    } else {
        __shared__ float red[256];
        int c = tid >> 1;
        int j = tid & 1;
        float we = 0.f;
        if (tid < 128) {
            #pragma unroll
            for (int i = 0; i < 16; i++) {
                float4 a = *(const float4*)&Wpt[c*PD + j*64 + i*4];
                float4 b = *(const float4*)&Wph[j*64 + i*4];
                we += a.x*b.x + a.y*b.y + a.z*b.z + a.w*b.w;
            }
            we += __shfl_xor_sync(0xffffffffu, we, 1);
            if (j == 0) d_gw[c] = gp[c] * we;
        }
        float v_sgw = (tid < 128 && j == 0) ? gp[c] * we : 0.f;
        float v_bc  = (tid < 128 && j == 0) ? bp[c] * we : 0.f;
        float v_bpt = (tid < 128) ? bpt[tid] * Wph[tid] : 0.f;

        red[tid] = v_sgw; __syncthreads();
        #pragma unroll
        for (int o = 128; o > 0; o >>= 1) { if (tid < o) red[tid] += red[tid+o]; __syncthreads(); }
        if (tid == 0) d_sgw = red[0];
        __syncthreads();
        red[tid] = v_bc + v_bpt; __syncthreads();
        #pragma unroll
        for (int o = 128; o > 0; o >>= 1) { if (tid < o) red[tid] += red[tid+o]; __syncthreads(); }
        if (tid == 0) d_bconst = red[0];
    }
}

// ---------------- K2: LayerNorm(F) -> Fn, vsum ------------------------------
__global__ void __launch_bounds__(256)
lnf_kernel(const float* __restrict__ F,
           const float* __restrict__ gf,
           const float* __restrict__ bf) {
    __shared__ float s_a[8], s_b[8];
    int r = blockIdx.x;
    int t = threadIdx.x;
    int w = t >> 5, l = t & 31;
    float x = F[r*FD + t];

    float sa = warp_sum(x);
    float sb = warp_sum(x*x);
    if (l == 0) { s_a[w] = sa; s_b[w] = sb; }
    __syncthreads();
    float ts = 0.f, tq = 0.f;
    #pragma unroll
    for (int i = 0; i < 8; i++) { ts += s_a[i]; tq += s_b[i]; }
    float mu = ts * (1.f/FD);
    float rstd = rsqrtf(tq * (1.f/FD) - mu*mu + EPSF);
    float fn = (x - mu) * rstd * gf[t] + bf[t];
    d_Fn[r*FD + t] = fn;

    __syncthreads();
    float sv = warp_sum(fn * d_wvsum[t]);
    if (l == 0) s_a[w] = sv;
    __syncthreads();
    if (t == 0) {
        float acc = 0.f;
        #pragma unroll
        for (int i = 0; i < 8; i++) acc += s_a[i];
        d_vsum[r] = acc;
    }
}

// ---------------- K3: fused  T = Fn @ M (first)  ||  bias(D sweep) ----------
__global__ void __launch_bounds__(256, 8)
bias_t_kernel(const float* __restrict__ Dm) {
    int tid = threadIdx.x;

    if (blockIdx.x >= T_TILES) {
        int w = tid >> 5, l = tid & 31;
        int sub = l & 7;          // column group: 2 float4 slots (32B)
        int rr  = l >> 3;         // row within group of 4

        float4 g0 = *(const float4*)&d_gw[sub*8];
        float4 g1 = *(const float4*)&d_gw[sub*8 + 4];
        float sgw = d_sgw, bconst = d_bconst;

        int rowbase = (blockIdx.x - T_TILES) * 256 + w * 32 + rr;
        #pragma unroll
        for (int it = 0; it < 8; it++) {
            int row = rowbase + it * 4;
            const float4* p = (const float4*)&Dm[(size_t)row * DP];
            float4 c0 = __ldcs(p + sub*2);
            float4 c1 = __ldcs(p + sub*2 + 1);

            float s1 = (c0.x+c0.y+c0.z+c0.w) + (c1.x+c1.y+c1.z+c1.w);
            float s2 = c0.x*c0.x+c0.y*c0.y+c0.z*c0.z+c0.w*c0.w
                     + c1.x*c1.x+c1.y*c1.y+c1.z*c1.z+c1.w*c1.w;
            float s3 = c0.x*g0.x+c0.y*g0.y+c0.z*g0.z+c0.w*g0.w
                     + c1.x*g1.x+c1.y*g1.y+c1.z*g1.z+c1.w*g1.w;

            #pragma unroll
            for (int o = 1; o < 8; o <<= 1) {
                s1 += __shfl_xor_sync(0xffffffffu, s1, o);
                s2 += __shfl_xor_sync(0xffffffffu, s2, o);
                s3 += __shfl_xor_sync(0xffffffffu, s3, o);
            }
            if (sub == 0) {
                float mu = s1 * (1.f/DP);
                float var = s2 * (1.f/DP) - mu*mu;
                float rstd = rsqrtf(var + EPSF);
                d_bias[row] = rstd * (s3 - mu*sgw) + bconst;
            }
        }
    } else {
        // ---- T[2048 x 256] = Fn[2048 x 256] @ M[256 x 256] (NN) ----
        __shared__ float As[16][68];
        __shared__ float Bs[16][68];
        int t2 = blockIdx.x;
        int bm = t2 & 31;
        int bn = t2 >> 5;
        int row0 = bm * 64;
        int n0   = bn * 64;

        int lm = tid >> 2;
        int lk = (tid & 3) * 4;
        int bk = tid >> 4;
        int bn4 = (tid & 15) * 4;
        int ty = tid >> 4, tx = tid & 15;

        float acc[4][4] = {};
        for (int kt = 0; kt < FD; kt += 16) {
            float4 a = *(const float4*)&d_Fn[(row0 + lm)*FD + kt + lk];
            As[lk+0][lm] = a.x; As[lk+1][lm] = a.y;
            As[lk+2][lm] = a.z; As[lk+3][lm] = a.w;
            float4 b = *(const float4*)&d_M[(kt + bk)*FD + n0 + bn4];
            Bs[bk][bn4+0] = b.x; Bs[bk][bn4+1] = b.y;
            Bs[bk][bn4+2] = b.z; Bs[bk][bn4+3] = b.w;
            __syncthreads();
            #pragma unroll
            for (int kf = 0; kf < 16; kf++) {
                float4 av = *(const float4*)&As[kf][ty*4];
                float4 bv = *(const float4*)&Bs[kf][tx*4];
                float aa[4] = {av.x, av.y, av.z, av.w};
                float bb[4] = {bv.x, bv.y, bv.z, bv.w};
                #pragma unroll
                for (int i = 0; i < 4; i++)
                    #pragma unroll
                    for (int j = 0; j < 4; j++)
                        acc[i][j] += aa[i] * bb[j];
            }
            __syncthreads();
        }
        #pragma unroll
        for (int i = 0; i < 4; i++) {
            int r = row0 + ty*4 + i;
            #pragma unroll
            for (int j = 0; j < 4; j++)
                d_T[r*FD + n0 + tx*4 + j] = acc[i][j];
        }
    }
}

// ---------------- K4: split-K(2) S-GEMM, 128x128 / 8x8, f32x2, dbl-buffer ---
// grid (4, 4, 8): z = b*2 + half. One __syncthreads per k-chunk iteration.
__global__ void __launch_bounds__(256)
s_gemm_kernel() {
    __shared__ float As[2][8][132];   // row stride 528B (16B-multiple)
    __shared__ float Bs[2][8][132];
    int z  = blockIdx.z;
    int b  = z >> 1;
    int half = z & 1;
    int q0 = blockIdx.y * 128;
    int k0 = blockIdx.x * 128;
    const float* A  = d_T  + b*NN*FD;
    const float* Bm = d_Fn + b*NN*FD;
    float* Sp = half ? d_Sb : d_Sa;

    int tid = threadIdx.x;
    int lrow = tid >> 1;            // 0..127
    int lk4  = (tid & 1) * 4;       // 0 or 4
    int ty = tid >> 4, tx = tid & 15;

    int kbase = half * 128;
    unsigned long long acc2[8][4] = {};   // (i, j-pair) packed f32x2

    // prologue: fill buffer 0
    {
        float4 pa = *(const float4*)&A [(q0 + lrow)*FD + kbase + lk4];
        float4 pb = *(const float4*)&Bm[(k0 + lrow)*FD + kbase + lk4];
        As[0][lk4+0][lrow] = pa.x; As[0][lk4+1][lrow] = pa.y;
        As[0][lk4+2][lrow] = pa.z; As[0][lk4+3][lrow] = pa.w;
        Bs[0][lk4+0][lrow] = pb.x; Bs[0][lk4+1][lrow] = pb.y;
        Bs[0][lk4+2][lrow] = pb.z; Bs[0][lk4+3][lrow] = pb.w;
    }
    __syncthreads();

    for (int c = 0; c < 16; c++) {
        int cur = c & 1, nxt = cur ^ 1;
        float4 pa, pb;
        if (c < 15) {
            int kt = kbase + (c + 1) * 8;
            pa = *(const float4*)&A [(q0 + lrow)*FD + kt + lk4];
            pb = *(const float4*)&Bm[(k0 + lrow)*FD + kt + lk4];
        }
        #pragma unroll
        for (int k = 0; k < 8; k++) {
            float a[8], bt[8];
            *(float4*)&a[0]  = *(const float4*)&As[cur][k][ty*8];
            *(float4*)&a[4]  = *(const float4*)&As[cur][k][ty*8 + 4];
            *(float4*)&bt[0] = *(const float4*)&Bs[cur][k][tx*8];
            *(float4*)&bt[4] = *(const float4*)&Bs[cur][k][tx*8 + 4];
            unsigned long long bp[4];
            #pragma unroll
            for (int j2 = 0; j2 < 4; j2++) bp[j2] = pack2(bt[2*j2], bt[2*j2+1]);
            #pragma unroll
            for (int i = 0; i < 8; i++) {
                unsigned long long ap = pack2(a[i], a[i]);
                #pragma unroll
                for (int j2 = 0; j2 < 4; j2++) ffma2(acc2[i][j2], ap, bp[j2]);
            }
        }
        if (c < 15) {
            As[nxt][lk4+0][lrow] = pa.x; As[nxt][lk4+1][lrow] = pa.y;
            As[nxt][lk4+2][lrow] = pa.z; As[nxt][lk4+3][lrow] = pa.w;
            Bs[nxt][lk4+0][lrow] = pb.x; Bs[nxt][lk4+1][lrow] = pb.y;
            Bs[nxt][lk4+2][lrow] = pb.z; Bs[nxt][lk4+3][lrow] = pb.w;
            __syncthreads();
        }
    }
    #pragma unroll
    for (int i = 0; i < 8; i++) {
        int q = q0 + ty*8 + i;
        int idx = (b*NN + q)*NN + k0 + tx*8;
        float2 p0 = unpack2(acc2[i][0]);
        float2 p1 = unpack2(acc2[i][1]);
        float2 p2 = unpack2(acc2[i][2]);
        float2 p3 = unpack2(acc2[i][3]);
        float4 o0, o1;
        o0.x = p0.x; o0.y = p0.y; o0.z = p1.x; o0.w = p1.y;
        o1.x = p2.x; o1.y = p2.y; o1.z = p3.x; o1.w = p3.y;
        *(float4*)&Sp[idx]     = o0;
        *(float4*)&Sp[idx + 4] = o1;
    }
}

// ---------------- K5: softmax, one warp per row -----------------------------
__global__ void __launch_bounds__(256)
softmax_out_kernel(float* __restrict__ out) {
    int wid = threadIdx.x >> 5, l = threadIdx.x & 31;
    int r = blockIdx.x * 8 + wid;
    int b = r >> 9;

    float s[16];
    #pragma unroll
    for (int c = 0; c < 4; c++) {
        int idx = r*NN + c*128 + l*4;
        float4 xa = *(const float4*)&d_Sa[idx];
        float4 xb = *(const float4*)&d_Sb[idx];
        float4 xc = *(const float4*)&d_bias[idx];
        s[c*4+0] = SCAL * (xa.x + xb.x + xc.x);
        s[c*4+1] = SCAL * (xa.y + xb.y + xc.y);
        s[c*4+2] = SCAL * (xa.z + xb.z + xc.z);
        s[c*4+3] = SCAL * (xa.w + xb.w + xc.w);
    }
    float m = s[0];
    #pragma unroll
    for (int i = 1; i < 16; i++) m = fmaxf(m, s[i]);
    m = warp_max(m);

    float se = 0.f, sv = 0.f;
    #pragma unroll
    for (int c = 0; c < 4; c++) {
        float4 vv = *(const float4*)&d_vsum[b*NN + c*128 + l*4];
        float e0 = __expf(s[c*4+0] - m);
        float e1 = __expf(s[c*4+1] - m);
        float e2 = __expf(s[c*4+2] - m);
        float e3 = __expf(s[c*4+3] - m);
        se += e0 + e1 + e2 + e3;
        sv += e0*vv.x + e1*vv.y + e2*vv.z + e3*vv.w;
    }
    se = warp_sum(se);
    sv = warp_sum(sv);
    if (l == 0) out[r] = sv / se;
}

// ---------------- launch ----------------------------------------------------
extern "C" void kernel_launch(void* const* d_in, const int* in_sizes, int n_in,
                              void* d_out, int out_size) {
    const float* F   = (const float*)d_in[0];
    const float* Dm  = (const float*)d_in[1];
    const float* Wq  = (const float*)d_in[2];
    const float* Wk  = (const float*)d_in[3];
    const float* Wv  = (const float*)d_in[4];
    const float* gf  = (const float*)d_in[5];
    const float* bf  = (const float*)d_in[6];
    const float* gp  = (const float*)d_in[7];
    const float* bp  = (const float*)d_in[8];
    const float* Wpt = (const float*)d_in[9];
    const float* bpt = (const float*)d_in[10];
    const float* Wph = (const float*)d_in[11];
    float* out = (float*)d_out;

    prep_mgemm_kernel<<<273, 256>>>(Wq, Wk, Wv, gp, bp, Wpt, bpt, Wph);
    lnf_kernel<<<ROWS, 256>>>(F, gf, bf);
    bias_t_kernel<<<T_TILES + BIAS_BLOCKS, 256>>>(Dm);
    dim3 g4(4, 4, BB*2);
    s_gemm_kernel<<<g4, 256>>>();
    softmax_out_kernel<<<ROWS/8, 256>>>(out);
}